// round 15
// baseline (speedup 1.0000x reference)
#include <cuda_runtime.h>
#include <cuda_fp16.h>
#include <math.h>
#include <float.h>

#define B_TOT   16384
#define NVOX    50000
#define MVIEW   12
#define FDIM    256
#define FAUG    272       // FDIM + 16 (extrinsics)
#define HEADS   8
#define QDIM    512       // HEADS*DK
#define ODIM    512       // HEADS*DV
#define PE3     24        // PE_ORDER*3
#define CDIM    2176      // HEADS*FAUG

#define PREP_ITEMS (PE3 * CDIM + ODIM * FDIM)     // 183296
#define PREP_BLOCKS (PREP_ITEMS / 256)            // 716 exactly

// ---------------- scratch (static device memory; no allocation) ----------------
__device__ float  g_mn[3];
__device__ float  g_rinv[3];
__device__ float  g_C2[PE3 * CDIM];                        // 209 KB
__device__ __half g_qWh[(size_t)B_TOT * CDIM];             // 71 MB
__device__ __half g_mixedh[(size_t)B_TOT * HEADS * FDIM];  // 67 MB
__device__ __half g_Wvt[ODIM * FDIM];                      // 512 KB  [h*64+n][k]

__device__ __forceinline__ unsigned su32(const void* p) {
    return (unsigned)__cvta_generic_to_shared(p);
}

// ---------------- K0: fused C2 + Wv transpose + vectorized min/max ----------------
__global__ void __launch_bounds__(256) k_prep(const float* __restrict__ Wq,
                                              const float* __restrict__ Wk,
                                              const float* __restrict__ Wv,
                                              const float* __restrict__ vox) {
    if (blockIdx.x < PREP_BLOCKS) {
        int i = blockIdx.x * 256 + threadIdx.x;
        if (i < PE3 * CDIM) {
            int j = i / CDIM;
            int col = i - j * CDIM;
            int h = col / FAUG;
            int f = col - h * FAUG;
            const float4* wq = (const float4*)(Wq + j * QDIM + h * 64);
            const float4* wk = (const float4*)(Wk + (size_t)f * QDIM + h * 64);
            float a0 = 0.f, a1 = 0.f, a2 = 0.f, a3 = 0.f;
            #pragma unroll
            for (int d = 0; d < 16; d++) {
                float4 q = wq[d], k = wk[d];
                a0 += q.x * k.x; a1 += q.y * k.y;
                a2 += q.z * k.z; a3 += q.w * k.w;
            }
            g_C2[i] = (a0 + a1) + (a2 + a3);
        } else {
            int t = i - PE3 * CDIM;
            int r = t >> 8, k = t & 255;
            g_Wvt[t] = __float2half(Wv[(size_t)k * ODIM + r]);
        }
        return;
    }

    // ---- last block: min/max over voxels, float4-vectorized ----
    __shared__ float red[8][6];
    int tid = threadIdx.x;
    float mn[3] = {FLT_MAX, FLT_MAX, FLT_MAX};
    float mx[3] = {-FLT_MAX, -FLT_MAX, -FLT_MAX};
    const float4* v4 = (const float4*)vox;
    for (int i = tid; i < 12500; i += 256) {
        float4 f0 = v4[3 * i];
        float4 f1 = v4[3 * i + 1];
        float4 f2 = v4[3 * i + 2];
        mn[0] = fminf(mn[0], fminf(fminf(f0.x, f0.w), fminf(f1.z, f2.y)));
        mx[0] = fmaxf(mx[0], fmaxf(fmaxf(f0.x, f0.w), fmaxf(f1.z, f2.y)));
        mn[1] = fminf(mn[1], fminf(fminf(f0.y, f1.x), fminf(f1.w, f2.z)));
        mx[1] = fmaxf(mx[1], fmaxf(fmaxf(f0.y, f1.x), fmaxf(f1.w, f2.z)));
        mn[2] = fminf(mn[2], fminf(fminf(f0.z, f1.y), fminf(f2.x, f2.w)));
        mx[2] = fmaxf(mx[2], fmaxf(fmaxf(f0.z, f1.y), fmaxf(f2.x, f2.w)));
    }
    #pragma unroll
    for (int c = 0; c < 3; c++) {
        #pragma unroll
        for (int o = 16; o > 0; o >>= 1) {
            mn[c] = fminf(mn[c], __shfl_xor_sync(0xffffffffu, mn[c], o));
            mx[c] = fmaxf(mx[c], __shfl_xor_sync(0xffffffffu, mx[c], o));
        }
    }
    if ((tid & 31) == 0) {
        #pragma unroll
        for (int c = 0; c < 3; c++) {
            red[tid >> 5][c]     = mn[c];
            red[tid >> 5][3 + c] = mx[c];
        }
    }
    __syncthreads();
    if (tid < 32) {
        int src = tid & 7;
        #pragma unroll
        for (int c = 0; c < 3; c++) { mn[c] = red[src][c]; mx[c] = red[src][3 + c]; }
        #pragma unroll
        for (int c = 0; c < 3; c++) {
            #pragma unroll
            for (int o = 4; o > 0; o >>= 1) {
                mn[c] = fminf(mn[c], __shfl_xor_sync(0xffffffffu, mn[c], o));
                mx[c] = fmaxf(mx[c], __shfl_xor_sync(0xffffffffu, mx[c], o));
            }
        }
        if (tid < 3) {
            g_mn[tid] = mn[tid];
            g_rinv[tid] = 1.0f / (mx[tid] - mn[tid]);
        }
    }
}

// ---------------- K2: qW = PE(xyz) @ C2 via HMMA, smem-staged output ----------
#define QLD 40    // halfs per A/B smem row
#define QLC 136   // halfs per staged-C row (272B = 17*16B)
#define QW_SMEM ((128 * QLD * 2 + 128 * QLC) * 2)
__global__ void __launch_bounds__(256) k_qw2h(const int* __restrict__ vidx,
                                              const float* __restrict__ vox) {
    extern __shared__ __half dsm[];
    __half* Ah = dsm;                       // [128][QLD]
    __half* Bh = dsm + 128 * QLD;           // [128][QLD]
    __half* Ch = dsm + 2 * 128 * QLD;       // [128][QLC] staged output
    int b0 = blockIdx.y * 128;
    int c0 = blockIdx.x * 128;
    int tid = threadIdx.x;

    if (tid < 128) {
        int idx = vidx[b0 + tid];
        float xn[3];
        #pragma unroll
        for (int c = 0; c < 3; c++)
            xn[c] = (vox[idx * 3 + c] - g_mn[c]) * g_rinv[c] - 0.5f;
        __half* ar = Ah + tid * QLD;
        float fr = 1.0f;
        #pragma unroll
        for (int p = 0; p < 8; p++) {
            ar[p * 3 + 0] = __float2half(sinf(xn[0] * fr));
            ar[p * 3 + 1] = __float2half(sinf(xn[1] * fr));
            ar[p * 3 + 2] = __float2half(sinf(xn[2] * fr));
            fr *= 2.0f;
        }
        #pragma unroll
        for (int k = PE3; k < 32; k++) ar[k] = __ushort_as_half(0);
    }
    for (int i = tid; i < 32 * 128; i += 256) {
        int k = i >> 7, c = i & 127;
        float v = (k < PE3) ? g_C2[k * CDIM + c0 + c] : 0.0f;
        Bh[c * QLD + k] = __float2half(v);
    }
    __syncthreads();

    int w = tid >> 5, lane = tid & 31;
    int m0 = w * 16;
    float acc[16][4] = {};

    unsigned aBase = su32(Ah + (m0 + (lane & 15)) * QLD + (lane >> 4) * 8);
    unsigned bBase = su32(Bh + (lane & 7) * QLD + ((lane >> 3) & 1) * 8);

    #pragma unroll
    for (int ks = 0; ks < 2; ks++) {
        unsigned a0, a1, a2, a3;
        asm volatile(
            "ldmatrix.sync.aligned.m8n8.x4.shared.b16 {%0,%1,%2,%3}, [%4];"
            : "=r"(a0), "=r"(a1), "=r"(a2), "=r"(a3)
            : "r"(aBase + ks * 32));
        #pragma unroll
        for (int nf = 0; nf < 16; nf++) {
            unsigned br0, br1;
            asm volatile(
                "ldmatrix.sync.aligned.m8n8.x2.shared.b16 {%0,%1}, [%2];"
                : "=r"(br0), "=r"(br1)
                : "r"(bBase + (unsigned)(nf * 8 * QLD * 2) + ks * 32));
            asm volatile(
                "mma.sync.aligned.m16n8k16.row.col.f32.f16.f16.f32 "
                "{%0,%1,%2,%3},{%4,%5,%6,%7},{%8,%9},{%0,%1,%2,%3};"
                : "+f"(acc[nf][0]), "+f"(acc[nf][1]),
                  "+f"(acc[nf][2]), "+f"(acc[nf][3])
                : "r"(a0), "r"(a1), "r"(a2), "r"(a3), "r"(br0), "r"(br1));
        }
    }

    int g = lane >> 2, tg = lane & 3;
    #pragma unroll
    for (int nf = 0; nf < 16; nf++) {
        int col = nf * 8 + 2 * tg;
        *(__half2*)&Ch[(m0 + g) * QLC + col] =
            __floats2half2_rn(acc[nf][0], acc[nf][1]);
        *(__half2*)&Ch[(m0 + g + 8) * QLC + col] =
            __floats2half2_rn(acc[nf][2], acc[nf][3]);
    }
    __syncthreads();
    #pragma unroll
    for (int j = 0; j < 8; j++) {
        int idx = tid + j * 256;
        int row = idx >> 4, c8 = (idx & 15) * 8;
        *(uint4*)&g_qWh[(size_t)(b0 + row) * CDIM + c0 + c8] =
            *(uint4*)&Ch[row * QLC + c8];
    }
}

// ---------------- K3: gather + HMMA logits + quad softmax + mix ----------------
#define SLD 296
__global__ void __launch_bounds__(256) k_attn(const int* __restrict__ vidx,
                                              const float* __restrict__ feats_g,
                                              const float* __restrict__ scores_g,
                                              const int* __restrict__ camids,
                                              const float* __restrict__ extr) {
    __shared__ __half sfq[16][SLD];    // B: view rows (feats|ext|0-pad), rows 12-15 zero
    __shared__ __half sq16[16][SLD];   // A: head rows (qW|0-pad), rows 8-15 zero
    __shared__ float  sp[HEADS][16];   // probabilities (cols 12-15 junk)
    __shared__ float  smask16[16];     // additive mask; 12-15 = -1e30
    __shared__ int    scam[MVIEW];

    int b = blockIdx.x;
    int tid = threadIdx.x;
    int idx = vidx[b];

    {
        uint4 z = make_uint4(0, 0, 0, 0);
        uint4* t0 = (uint4*)&sfq[0][0];
        uint4* t1 = (uint4*)&sq16[0][0];
        for (int i = tid; i < 16 * SLD / 8; i += 256) { t0[i] = z; t1[i] = z; }
    }
    __syncthreads();

    const float4* fsrc = (const float4*)(feats_g + (size_t)idx * MVIEW * FDIM);
    #pragma unroll
    for (int ii = 0; ii < 3; ii++) {
        int i = tid + ii * 256;
        float4 v = fsrc[i];
        int m = i >> 6, t4 = (i & 63) * 4;
        __half2 lo = __floats2half2_rn(v.x, v.y);
        __half2 hi = __floats2half2_rn(v.z, v.w);
        *(uint2*)&sfq[m][t4] = make_uint2(*(unsigned*)&lo, *(unsigned*)&hi);
    }
    for (int i = tid; i < HEADS * 34; i += 256) {
        int h = i / 34, j = i - h * 34;
        *(uint4*)&sq16[h][j * 8] =
            *(const uint4*)&g_qWh[(size_t)b * CDIM + h * FAUG + j * 8];
    }
    if (tid < 16) {
        float mk = -1e30f;
        if (tid < MVIEW) {
            float s = scores_g[(size_t)idx * MVIEW + tid];
            mk = (s < 0.0f) ? -1e30f : 0.0f;
            scam[tid] = camids[(size_t)idx * MVIEW + tid];
        }
        smask16[tid] = mk;
    }
    __syncthreads();
    if (tid < MVIEW * 16) {
        int m = tid >> 4, j = tid & 15;
        sfq[m][FDIM + j] = __float2half(extr[scam[m] * 16 + j]);
    }
    __syncthreads();

    int w = tid >> 5, lane = tid & 31;

    if (w == 0) {
        float acc[2][4] = {};
        unsigned aBase = su32(&sq16[lane & 15][(lane >> 4) * 8]);
        unsigned bBase = su32(&sfq[lane & 7][((lane >> 3) & 1) * 8]);
        #pragma unroll
        for (int ks = 0; ks < 18; ks++) {
            unsigned a0, a1, a2, a3;
            asm volatile(
                "ldmatrix.sync.aligned.m8n8.x4.shared.b16 {%0,%1,%2,%3}, [%4];"
                : "=r"(a0), "=r"(a1), "=r"(a2), "=r"(a3)
                : "r"(aBase + ks * 32));
            #pragma unroll
            for (int nf = 0; nf < 2; nf++) {
                unsigned br0, br1;
                asm volatile(
                    "ldmatrix.sync.aligned.m8n8.x2.shared.b16 {%0,%1}, [%2];"
                    : "=r"(br0), "=r"(br1)
                    : "r"(bBase + (unsigned)(nf * 8 * SLD * 2) + ks * 32));
                asm volatile(
                    "mma.sync.aligned.m16n8k16.row.col.f32.f16.f16.f32 "
                    "{%0,%1,%2,%3},{%4,%5,%6,%7},{%8,%9},{%0,%1,%2,%3};"
                    : "+f"(acc[nf][0]), "+f"(acc[nf][1]),
                      "+f"(acc[nf][2]), "+f"(acc[nf][3])
                    : "r"(a0), "r"(a1), "r"(a2), "r"(a3), "r"(br0), "r"(br1));
            }
        }
        int g = lane >> 2, tg = lane & 3;
        float l0 = acc[0][0] * 0.125f + smask16[2 * tg];
        float l1 = acc[0][1] * 0.125f + smask16[2 * tg + 1];
        float l2 = acc[1][0] * 0.125f + smask16[8 + 2 * tg];
        float l3 = acc[1][1] * 0.125f + smask16[9 + 2 * tg];
        float mx = fmaxf(fmaxf(l0, l1), fmaxf(l2, l3));
        mx = fmaxf(mx, __shfl_xor_sync(0xffffffffu, mx, 1));
        mx = fmaxf(mx, __shfl_xor_sync(0xffffffffu, mx, 2));
        float e0 = __expf(l0 - mx), e1 = __expf(l1 - mx);
        float e2 = __expf(l2 - mx), e3 = __expf(l3 - mx);
        float sum = (e0 + e1) + (e2 + e3);
        sum += __shfl_xor_sync(0xffffffffu, sum, 1);
        sum += __shfl_xor_sync(0xffffffffu, sum, 2);
        float inv = 1.0f / sum;
        sp[g][2 * tg]     = e0 * inv;
        sp[g][2 * tg + 1] = e1 * inv;
        sp[g][8 + 2 * tg] = e2 * inv;
        sp[g][9 + 2 * tg] = e3 * inv;
    }
    __syncthreads();

    int part = tid >> 7;
    int t2 = (tid & 127) * 2;
    float2 fv2[MVIEW];
    #pragma unroll
    for (int m = 0; m < MVIEW; m++)
        fv2[m] = __half22float2(*(__half2*)&sfq[m][t2]);
    #pragma unroll
    for (int hh = 0; hh < 4; hh++) {
        int h = hh * 2 + part;
        float a0 = 0.0f, a1 = 0.0f;
        #pragma unroll
        for (int m = 0; m < MVIEW; m++) {
            float p = sp[h][m];
            a0 += p * fv2[m].x;
            a1 += p * fv2[m].y;
        }
        *(__half2*)&g_mixedh[((size_t)b * HEADS + h) * FDIM + t2] =
            __floats2half2_rn(a0, a1);
    }
}

// ---------------- K4: out = mixedh @ Wvt (HMMA), 64-row tiles, 128 threads ------
#define LDA 264
#define LDC2 68   // floats per staged-C row (272B)
#define OUT_SMEM_H ((64 * LDA + 64 * LDA) * 2)
__global__ void __launch_bounds__(128) k_out_hmma(float* __restrict__ out) {
    extern __shared__ __half smh[];
    __half* Ah = smh;                // [64][LDA]
    __half* Bt = smh + 64 * LDA;     // [64][LDA]
    float*  Cf = (float*)smh;        // reused after MMA: [64][LDC2]
    int h = blockIdx.y;
    int b0 = blockIdx.x * 64;
    int tid = threadIdx.x;

    for (int i = tid; i < 64 * 32; i += 128) {
        int r = i >> 5, c8 = (i & 31) * 8;
        *(uint4*)&Ah[r * LDA + c8] =
            *(const uint4*)&g_mixedh[((size_t)(b0 + r) * HEADS + h) * FDIM + c8];
    }
    for (int i = tid; i < 64 * 32; i += 128) {
        int r = i >> 5, c8 = (i & 31) * 8;
        *(uint4*)&Bt[r * LDA + c8] =
            *(const uint4*)&g_Wvt[(size_t)(h * 64 + r) * FDIM + c8];
    }
    __syncthreads();

    int w = tid >> 5, lane = tid & 31;
    int m0 = w * 16;
    float acc[8][4] = {};

    unsigned aBase = su32(Ah + (m0 + (lane & 15)) * LDA + (lane >> 4) * 8);
    unsigned bBase = su32(Bt + (lane & 7) * LDA + ((lane >> 3) & 1) * 8);

    #pragma unroll
    for (int ks = 0; ks < 16; ks++) {
        unsigned a0, a1, a2, a3;
        asm volatile(
            "ldmatrix.sync.aligned.m8n8.x4.shared.b16 {%0,%1,%2,%3}, [%4];"
            : "=r"(a0), "=r"(a1), "=r"(a2), "=r"(a3)
            : "r"(aBase + ks * 32));
        #pragma unroll
        for (int nf = 0; nf < 8; nf++) {
            unsigned br0, br1;
            asm volatile(
                "ldmatrix.sync.aligned.m8n8.x2.shared.b16 {%0,%1}, [%2];"
                : "=r"(br0), "=r"(br1)
                : "r"(bBase + (unsigned)(nf * 8 * LDA * 2) + ks * 32));
            asm volatile(
                "mma.sync.aligned.m16n8k16.row.col.f32.f16.f16.f32 "
                "{%0,%1,%2,%3},{%4,%5,%6,%7},{%8,%9},{%0,%1,%2,%3};"
                : "+f"(acc[nf][0]), "+f"(acc[nf][1]),
                  "+f"(acc[nf][2]), "+f"(acc[nf][3])
                : "r"(a0), "r"(a1), "r"(a2), "r"(a3), "r"(br0), "r"(br1));
        }
    }

    // stage to smem (reuse Ah region), then coalesced STG.128
    __syncthreads();
    int g = lane >> 2, tg = lane & 3;
    #pragma unroll
    for (int nf = 0; nf < 8; nf++) {
        int col = nf * 8 + 2 * tg;
        *(float2*)&Cf[(m0 + g) * LDC2 + col] = make_float2(acc[nf][0], acc[nf][1]);
        *(float2*)&Cf[(m0 + g + 8) * LDC2 + col] = make_float2(acc[nf][2], acc[nf][3]);
    }
    __syncthreads();
    #pragma unroll
    for (int j = 0; j < 8; j++) {
        int idx = tid + j * 128;
        int row = idx >> 4, c4 = (idx & 15) * 4;
        *(float4*)&out[(size_t)(b0 + row) * ODIM + h * 64 + c4] =
            *(float4*)&Cf[row * LDC2 + c4];
    }
}

// ---------------- launcher ----------------
extern "C" void kernel_launch(void* const* d_in, const int* in_sizes, int n_in,
                              void* d_out, int out_size) {
    const int*   vidx = (const int*)d_in[0];
    const float* vox  = (const float*)d_in[1];
    const float* vf   = (const float*)d_in[2];
    const float* vs   = (const float*)d_in[3];
    const int*   cam  = (const int*)d_in[4];
    const float* ext  = (const float*)d_in[5];
    const float* Wq   = (const float*)d_in[6];
    const float* Wk   = (const float*)d_in[7];
    const float* Wv   = (const float*)d_in[8];
    float* out = (float*)d_out;

    cudaFuncSetAttribute(k_qw2h, cudaFuncAttributeMaxDynamicSharedMemorySize,
                         QW_SMEM);
    cudaFuncSetAttribute(k_out_hmma, cudaFuncAttributeMaxDynamicSharedMemorySize,
                         OUT_SMEM_H);

    k_prep<<<PREP_BLOCKS + 1, 256>>>(Wq, Wk, Wv, vox);
    k_qw2h<<<dim3(CDIM / 128, B_TOT / 128), 256, QW_SMEM>>>(vidx, vox);
    k_attn<<<B_TOT, 256>>>(vidx, vf, vs, cam, ext);
    k_out_hmma<<<dim3(B_TOT / 64, HEADS), 128, OUT_SMEM_H>>>(out);
}

// round 17
// speedup vs baseline: 1.1834x; 1.1834x over previous
#include <cuda_runtime.h>
#include <cuda_fp16.h>
#include <math.h>
#include <float.h>

#define B_TOT   16384
#define NVOX    50000
#define MVIEW   12
#define FDIM    256
#define FAUG    272       // FDIM + 16 (extrinsics)
#define HEADS   8
#define QDIM    512       // HEADS*DK
#define ODIM    512       // HEADS*DV
#define PE3     24        // PE_ORDER*3
#define CDIM    2176      // HEADS*FAUG

// ---------------- scratch (static device memory; no allocation) ----------------
__device__ float  g_mn[3];
__device__ float  g_rinv[3];
__device__ float  g_C2[PE3 * CDIM];                        // 209 KB
__device__ __half g_qWh[(size_t)B_TOT * CDIM];             // 71 MB
__device__ __half g_mixedh[(size_t)B_TOT * HEADS * FDIM];  // 67 MB
__device__ __half g_Wvt[ODIM * FDIM];                      // 512 KB  [h*64+n][k]

__device__ __forceinline__ unsigned su32(const void* p) {
    return (unsigned)__cvta_generic_to_shared(p);
}

// ---------------- K0: fused C2 + Wv transpose prep ----------------
__global__ void __launch_bounds__(256) k_prep(const float* __restrict__ Wq,
                                              const float* __restrict__ Wk,
                                              const float* __restrict__ Wv) {
    int i = blockIdx.x * 256 + threadIdx.x;
    if (i < PE3 * CDIM) {
        int j = i / CDIM;
        int col = i - j * CDIM;
        int h = col / FAUG;
        int f = col - h * FAUG;
        const float4* wq = (const float4*)(Wq + j * QDIM + h * 64);
        const float4* wk = (const float4*)(Wk + (size_t)f * QDIM + h * 64);
        float a0 = 0.f, a1 = 0.f, a2 = 0.f, a3 = 0.f;
        #pragma unroll
        for (int d = 0; d < 16; d++) {
            float4 q = wq[d], k = wk[d];
            a0 += q.x * k.x; a1 += q.y * k.y;
            a2 += q.z * k.z; a3 += q.w * k.w;
        }
        g_C2[i] = (a0 + a1) + (a2 + a3);
    } else {
        int t = i - PE3 * CDIM;
        if (t < ODIM * FDIM) {
            int r = t >> 8, k = t & 255;
            g_Wvt[t] = __float2half(Wv[(size_t)k * ODIM + r]);
        }
    }
}

// ---------------- K1: single-block min/max, float4-vectorized ----------------
__global__ void __launch_bounds__(256) k_minmax(const float* __restrict__ vox) {
    __shared__ float red[8][6];
    int tid = threadIdx.x;
    float mn[3] = {FLT_MAX, FLT_MAX, FLT_MAX};
    float mx[3] = {-FLT_MAX, -FLT_MAX, -FLT_MAX};
    const float4* v4 = (const float4*)vox;
    for (int i = tid; i < 12500; i += 256) {
        float4 f0 = v4[3 * i];
        float4 f1 = v4[3 * i + 1];
        float4 f2 = v4[3 * i + 2];
        mn[0] = fminf(mn[0], fminf(fminf(f0.x, f0.w), fminf(f1.z, f2.y)));
        mx[0] = fmaxf(mx[0], fmaxf(fmaxf(f0.x, f0.w), fmaxf(f1.z, f2.y)));
        mn[1] = fminf(mn[1], fminf(fminf(f0.y, f1.x), fminf(f1.w, f2.z)));
        mx[1] = fmaxf(mx[1], fmaxf(fmaxf(f0.y, f1.x), fmaxf(f1.w, f2.z)));
        mn[2] = fminf(mn[2], fminf(fminf(f0.z, f1.y), fminf(f2.x, f2.w)));
        mx[2] = fmaxf(mx[2], fmaxf(fmaxf(f0.z, f1.y), fmaxf(f2.x, f2.w)));
    }
    #pragma unroll
    for (int c = 0; c < 3; c++) {
        #pragma unroll
        for (int o = 16; o > 0; o >>= 1) {
            mn[c] = fminf(mn[c], __shfl_xor_sync(0xffffffffu, mn[c], o));
            mx[c] = fmaxf(mx[c], __shfl_xor_sync(0xffffffffu, mx[c], o));
        }
    }
    if ((tid & 31) == 0) {
        #pragma unroll
        for (int c = 0; c < 3; c++) {
            red[tid >> 5][c]     = mn[c];
            red[tid >> 5][3 + c] = mx[c];
        }
    }
    __syncthreads();
    if (tid < 32) {
        int src = tid & 7;
        #pragma unroll
        for (int c = 0; c < 3; c++) { mn[c] = red[src][c]; mx[c] = red[src][3 + c]; }
        #pragma unroll
        for (int c = 0; c < 3; c++) {
            #pragma unroll
            for (int o = 4; o > 0; o >>= 1) {
                mn[c] = fminf(mn[c], __shfl_xor_sync(0xffffffffu, mn[c], o));
                mx[c] = fmaxf(mx[c], __shfl_xor_sync(0xffffffffu, mx[c], o));
            }
        }
        if (tid < 3) {
            g_mn[tid] = mn[tid];
            g_rinv[tid] = 1.0f / (mx[tid] - mn[tid]);
        }
    }
}

// ---------------- K2: qW = PE(xyz) @ C2 via HMMA, smem-staged output ----------
#define QLD 40    // halfs per A/B smem row
#define QLC 136   // halfs per staged-C row (272B = 17*16B)
#define QW_SMEM ((128 * QLD * 2 + 128 * QLC) * 2)
__global__ void __launch_bounds__(256) k_qw2h(const int* __restrict__ vidx,
                                              const float* __restrict__ vox) {
    extern __shared__ __half dsm[];
    __half* Ah = dsm;                       // [128][QLD]
    __half* Bh = dsm + 128 * QLD;           // [128][QLD]
    __half* Ch = dsm + 2 * 128 * QLD;       // [128][QLC] staged output
    int b0 = blockIdx.y * 128;
    int c0 = blockIdx.x * 128;
    int tid = threadIdx.x;

    if (tid < 128) {
        int idx = vidx[b0 + tid];
        float xn[3];
        #pragma unroll
        for (int c = 0; c < 3; c++)
            xn[c] = (vox[idx * 3 + c] - g_mn[c]) * g_rinv[c] - 0.5f;
        __half* ar = Ah + tid * QLD;
        float fr = 1.0f;
        #pragma unroll
        for (int p = 0; p < 8; p++) {
            ar[p * 3 + 0] = __float2half(sinf(xn[0] * fr));
            ar[p * 3 + 1] = __float2half(sinf(xn[1] * fr));
            ar[p * 3 + 2] = __float2half(sinf(xn[2] * fr));
            fr *= 2.0f;
        }
        #pragma unroll
        for (int k = PE3; k < 32; k++) ar[k] = __ushort_as_half(0);
    }
    for (int i = tid; i < 32 * 128; i += 256) {
        int k = i >> 7, c = i & 127;
        float v = (k < PE3) ? g_C2[k * CDIM + c0 + c] : 0.0f;
        Bh[c * QLD + k] = __float2half(v);
    }
    __syncthreads();

    int w = tid >> 5, lane = tid & 31;
    int m0 = w * 16;
    float acc[16][4] = {};

    unsigned aBase = su32(Ah + (m0 + (lane & 15)) * QLD + (lane >> 4) * 8);
    unsigned bBase = su32(Bh + (lane & 7) * QLD + ((lane >> 3) & 1) * 8);

    #pragma unroll
    for (int ks = 0; ks < 2; ks++) {
        unsigned a0, a1, a2, a3;
        asm volatile(
            "ldmatrix.sync.aligned.m8n8.x4.shared.b16 {%0,%1,%2,%3}, [%4];"
            : "=r"(a0), "=r"(a1), "=r"(a2), "=r"(a3)
            : "r"(aBase + ks * 32));
        #pragma unroll
        for (int nf = 0; nf < 16; nf++) {
            unsigned br0, br1;
            asm volatile(
                "ldmatrix.sync.aligned.m8n8.x2.shared.b16 {%0,%1}, [%2];"
                : "=r"(br0), "=r"(br1)
                : "r"(bBase + (unsigned)(nf * 8 * QLD * 2) + ks * 32));
            asm volatile(
                "mma.sync.aligned.m16n8k16.row.col.f32.f16.f16.f32 "
                "{%0,%1,%2,%3},{%4,%5,%6,%7},{%8,%9},{%0,%1,%2,%3};"
                : "+f"(acc[nf][0]), "+f"(acc[nf][1]),
                  "+f"(acc[nf][2]), "+f"(acc[nf][3])
                : "r"(a0), "r"(a1), "r"(a2), "r"(a3), "r"(br0), "r"(br1));
        }
    }

    int g = lane >> 2, tg = lane & 3;
    #pragma unroll
    for (int nf = 0; nf < 16; nf++) {
        int col = nf * 8 + 2 * tg;
        *(__half2*)&Ch[(m0 + g) * QLC + col] =
            __floats2half2_rn(acc[nf][0], acc[nf][1]);
        *(__half2*)&Ch[(m0 + g + 8) * QLC + col] =
            __floats2half2_rn(acc[nf][2], acc[nf][3]);
    }
    __syncthreads();
    #pragma unroll
    for (int j = 0; j < 8; j++) {
        int idx = tid + j * 256;
        int row = idx >> 4, c8 = (idx & 15) * 8;
        *(uint4*)&g_qWh[(size_t)(b0 + row) * CDIM + c0 + c8] =
            *(uint4*)&Ch[row * QLC + c8];
    }
}

// ---------------- K3: gather + HMMA logits + quad softmax + mix ----------------
#define SLD 296
__global__ void __launch_bounds__(256) k_attn(const int* __restrict__ vidx,
                                              const float* __restrict__ feats_g,
                                              const float* __restrict__ scores_g,
                                              const int* __restrict__ camids,
                                              const float* __restrict__ extr) {
    __shared__ __half sfq[16][SLD];    // B: view rows (feats|ext|0-pad), rows 12-15 zero
    __shared__ __half sq16[16][SLD];   // A: head rows (qW|0-pad), rows 8-15 zero
    __shared__ float  sp[HEADS][16];   // probabilities (cols 12-15 junk)
    __shared__ float  smask16[16];     // additive mask; 12-15 = -1e30
    __shared__ int    scam[MVIEW];

    int b = blockIdx.x;
    int tid = threadIdx.x;
    int idx = vidx[b];

    {
        uint4 z = make_uint4(0, 0, 0, 0);
        uint4* t0 = (uint4*)&sfq[0][0];
        uint4* t1 = (uint4*)&sq16[0][0];
        for (int i = tid; i < 16 * SLD / 8; i += 256) { t0[i] = z; t1[i] = z; }
    }
    __syncthreads();

    const float4* fsrc = (const float4*)(feats_g + (size_t)idx * MVIEW * FDIM);
    #pragma unroll
    for (int ii = 0; ii < 3; ii++) {
        int i = tid + ii * 256;
        float4 v = fsrc[i];
        int m = i >> 6, t4 = (i & 63) * 4;
        __half2 lo = __floats2half2_rn(v.x, v.y);
        __half2 hi = __floats2half2_rn(v.z, v.w);
        *(uint2*)&sfq[m][t4] = make_uint2(*(unsigned*)&lo, *(unsigned*)&hi);
    }
    for (int i = tid; i < HEADS * 34; i += 256) {
        int h = i / 34, j = i - h * 34;
        *(uint4*)&sq16[h][j * 8] =
            *(const uint4*)&g_qWh[(size_t)b * CDIM + h * FAUG + j * 8];
    }
    if (tid < 16) {
        float mk = -1e30f;
        if (tid < MVIEW) {
            float s = scores_g[(size_t)idx * MVIEW + tid];
            mk = (s < 0.0f) ? -1e30f : 0.0f;
            scam[tid] = camids[(size_t)idx * MVIEW + tid];
        }
        smask16[tid] = mk;
    }
    __syncthreads();
    if (tid < MVIEW * 16) {
        int m = tid >> 4, j = tid & 15;
        sfq[m][FDIM + j] = __float2half(extr[scam[m] * 16 + j]);
    }
    __syncthreads();

    int w = tid >> 5, lane = tid & 31;

    if (w == 0) {
        float acc[2][4] = {};
        unsigned aBase = su32(&sq16[lane & 15][(lane >> 4) * 8]);
        unsigned bBase = su32(&sfq[lane & 7][((lane >> 3) & 1) * 8]);
        #pragma unroll
        for (int ks = 0; ks < 18; ks++) {
            unsigned a0, a1, a2, a3;
            asm volatile(
                "ldmatrix.sync.aligned.m8n8.x4.shared.b16 {%0,%1,%2,%3}, [%4];"
                : "=r"(a0), "=r"(a1), "=r"(a2), "=r"(a3)
                : "r"(aBase + ks * 32));
            #pragma unroll
            for (int nf = 0; nf < 2; nf++) {
                unsigned br0, br1;
                asm volatile(
                    "ldmatrix.sync.aligned.m8n8.x2.shared.b16 {%0,%1}, [%2];"
                    : "=r"(br0), "=r"(br1)
                    : "r"(bBase + (unsigned)(nf * 8 * SLD * 2) + ks * 32));
                asm volatile(
                    "mma.sync.aligned.m16n8k16.row.col.f32.f16.f16.f32 "
                    "{%0,%1,%2,%3},{%4,%5,%6,%7},{%8,%9},{%0,%1,%2,%3};"
                    : "+f"(acc[nf][0]), "+f"(acc[nf][1]),
                      "+f"(acc[nf][2]), "+f"(acc[nf][3])
                    : "r"(a0), "r"(a1), "r"(a2), "r"(a3), "r"(br0), "r"(br1));
            }
        }
        int g = lane >> 2, tg = lane & 3;
        float l0 = acc[0][0] * 0.125f + smask16[2 * tg];
        float l1 = acc[0][1] * 0.125f + smask16[2 * tg + 1];
        float l2 = acc[1][0] * 0.125f + smask16[8 + 2 * tg];
        float l3 = acc[1][1] * 0.125f + smask16[9 + 2 * tg];
        float mx = fmaxf(fmaxf(l0, l1), fmaxf(l2, l3));
        mx = fmaxf(mx, __shfl_xor_sync(0xffffffffu, mx, 1));
        mx = fmaxf(mx, __shfl_xor_sync(0xffffffffu, mx, 2));
        float e0 = __expf(l0 - mx), e1 = __expf(l1 - mx);
        float e2 = __expf(l2 - mx), e3 = __expf(l3 - mx);
        float sum = (e0 + e1) + (e2 + e3);
        sum += __shfl_xor_sync(0xffffffffu, sum, 1);
        sum += __shfl_xor_sync(0xffffffffu, sum, 2);
        float inv = 1.0f / sum;
        sp[g][2 * tg]     = e0 * inv;
        sp[g][2 * tg + 1] = e1 * inv;
        sp[g][8 + 2 * tg] = e2 * inv;
        sp[g][9 + 2 * tg] = e3 * inv;
    }
    __syncthreads();

    int part = tid >> 7;
    int t2 = (tid & 127) * 2;
    float2 fv2[MVIEW];
    #pragma unroll
    for (int m = 0; m < MVIEW; m++)
        fv2[m] = __half22float2(*(__half2*)&sfq[m][t2]);
    #pragma unroll
    for (int hh = 0; hh < 4; hh++) {
        int h = hh * 2 + part;
        float a0 = 0.0f, a1 = 0.0f;
        #pragma unroll
        for (int m = 0; m < MVIEW; m++) {
            float p = sp[h][m];
            a0 += p * fv2[m].x;
            a1 += p * fv2[m].y;
        }
        *(__half2*)&g_mixedh[((size_t)b * HEADS + h) * FDIM + t2] =
            __floats2half2_rn(a0, a1);
    }
}

// ---------------- K4: out = mixedh @ Wvt, persistent (4 chunks/CTA) -----------
#define LDA 264
#define LDC2 68   // floats per staged-C row (272B)
#define OUT_SMEM_H ((64 * LDA + 128 * LDA) * 2)
__global__ void __launch_bounds__(256) k_out_hmma(float* __restrict__ out) {
    extern __shared__ __half smh[];
    __half* Bt = smh;                // [64][LDA]  Wv_h slice (resident)
    __half* Ah = smh + 64 * LDA;     // [128][LDA]
    float*  Cf = (float*)Ah;         // reused after MMA: [128][LDC2]
    int h = blockIdx.y;
    int tid = threadIdx.x;
    int w = tid >> 5, lane = tid & 31;
    int m0 = w * 16;

    // load B once
    for (int i = tid; i < 64 * 32; i += 256) {
        int r = i >> 5, c8 = (i & 31) * 8;
        *(uint4*)&Bt[r * LDA + c8] =
            *(const uint4*)&g_Wvt[(size_t)(h * 64 + r) * FDIM + c8];
    }

    unsigned aBase = su32(Ah + (m0 + (lane & 15)) * LDA + (lane >> 4) * 8);
    unsigned bBase = su32(Bt + (lane & 7) * LDA + ((lane >> 3) & 1) * 8);
    int g = lane >> 2, tg = lane & 3;

    #pragma unroll 1
    for (int chunk = 0; chunk < 4; chunk++) {
        int b0 = (blockIdx.x * 4 + chunk) * 128;
        __syncthreads();   // B ready (chunk 0) / previous store done (Cf aliases Ah)
        for (int i = tid; i < 128 * 32; i += 256) {
            int r = i >> 5, c8 = (i & 31) * 8;
            *(uint4*)&Ah[r * LDA + c8] =
                *(const uint4*)&g_mixedh[((size_t)(b0 + r) * HEADS + h) * FDIM + c8];
        }
        __syncthreads();

        float acc[8][4] = {};
        #pragma unroll
        for (int ks = 0; ks < 16; ks++) {
            unsigned a0, a1, a2, a3;
            asm volatile(
                "ldmatrix.sync.aligned.m8n8.x4.shared.b16 {%0,%1,%2,%3}, [%4];"
                : "=r"(a0), "=r"(a1), "=r"(a2), "=r"(a3)
                : "r"(aBase + ks * 32));
            #pragma unroll
            for (int nf = 0; nf < 8; nf++) {
                unsigned br0, br1;
                asm volatile(
                    "ldmatrix.sync.aligned.m8n8.x2.shared.b16 {%0,%1}, [%2];"
                    : "=r"(br0), "=r"(br1)
                    : "r"(bBase + (unsigned)(nf * 8 * LDA * 2) + ks * 32));
                asm volatile(
                    "mma.sync.aligned.m16n8k16.row.col.f32.f16.f16.f32 "
                    "{%0,%1,%2,%3},{%4,%5,%6,%7},{%8,%9},{%0,%1,%2,%3};"
                    : "+f"(acc[nf][0]), "+f"(acc[nf][1]),
                      "+f"(acc[nf][2]), "+f"(acc[nf][3])
                    : "r"(a0), "r"(a1), "r"(a2), "r"(a3), "r"(br0), "r"(br1));
            }
        }

        __syncthreads();   // all ldmatrix reads of Ah done before Cf overwrite
        #pragma unroll
        for (int nf = 0; nf < 8; nf++) {
            int col = nf * 8 + 2 * tg;
            *(float2*)&Cf[(m0 + g) * LDC2 + col] =
                make_float2(acc[nf][0], acc[nf][1]);
            *(float2*)&Cf[(m0 + g + 8) * LDC2 + col] =
                make_float2(acc[nf][2], acc[nf][3]);
        }
        __syncthreads();
        #pragma unroll
        for (int j = 0; j < 8; j++) {
            int idx = tid + j * 256;
            int row = idx >> 4, c4 = (idx & 15) * 4;
            *(float4*)&out[(size_t)(b0 + row) * ODIM + h * 64 + c4] =
                *(float4*)&Cf[row * LDC2 + c4];
        }
    }
}

// ---------------- launcher ----------------
extern "C" void kernel_launch(void* const* d_in, const int* in_sizes, int n_in,
                              void* d_out, int out_size) {
    const int*   vidx = (const int*)d_in[0];
    const float* vox  = (const float*)d_in[1];
    const float* vf   = (const float*)d_in[2];
    const float* vs   = (const float*)d_in[3];
    const int*   cam  = (const int*)d_in[4];
    const float* ext  = (const float*)d_in[5];
    const float* Wq   = (const float*)d_in[6];
    const float* Wk   = (const float*)d_in[7];
    const float* Wv   = (const float*)d_in[8];
    float* out = (float*)d_out;

    cudaFuncSetAttribute(k_qw2h, cudaFuncAttributeMaxDynamicSharedMemorySize,
                         QW_SMEM);
    cudaFuncSetAttribute(k_out_hmma, cudaFuncAttributeMaxDynamicSharedMemorySize,
                         OUT_SMEM_H);

    k_prep<<<(PE3 * CDIM + ODIM * FDIM + 255) / 256, 256>>>(Wq, Wk, Wv);
    k_minmax<<<1, 256>>>(vox);
    k_qw2h<<<dim3(CDIM / 128, B_TOT / 128), 256, QW_SMEM>>>(vidx, vox);
    k_attn<<<B_TOT, 256>>>(vidx, vf, vs, cam, ext);
    k_out_hmma<<<dim3(32, HEADS), 256, OUT_SMEM_H>>>(out);
}